// round 4
// baseline (speedup 1.0000x reference)
#include <cuda_runtime.h>
#include <math.h>

// Problem constants
#define B_  4
#define T_  4096
#define D_  1024
#define H_  16
#define HD_ 64
#define M_  (B_ * T_)   // 16384 rows

// ---------------- scratch (device globals; no allocation allowed) ----------
// g_KT doubles as 'tmp' for the output GEMM (K dead after kv_reduce).
__device__ float g_Q[M_ * D_];
__device__ float g_KT[M_ * D_];
__device__ float g_V[M_ * D_];
__device__ float g_kv[B_ * H_ * HD_ * HD_];
__device__ float g_ksum[B_ * H_ * HD_];
__device__ unsigned char g_mask[M_];   // canonical 0/1 per (b*T + t)

// ---------------------------------------------------------------------------
// Canonicalize the mask regardless of its physical dtype.
// Detection from byte patterns over the first M_ bytes (always in-bounds):
//   float32 (1.0f = 00 00 80 3F): bytes 0x80 / 0x3F appear          -> word test
//   bool/int8 (random 0/1):       nonzero bytes at offsets %4 != 0  -> byte test
//   int32 (1 = 01 00 00 00):      nonzero only at offsets %4 == 0   -> word test
// All-zero mask: any mode gives the same (empty) mask.
// ---------------------------------------------------------------------------
__global__ void mask_canon(const unsigned char* __restrict__ mraw)
{
    __shared__ int s_float, s_byte;
    const int tid = threadIdx.x;          // single block, 1024 threads
    if (tid == 0) { s_float = 0; s_byte = 0; }
    __syncthreads();

    int lf = 0, lb = 0;
    for (int i = tid; i < M_; i += 1024) {
        const unsigned char c = mraw[i];
        if (c == 0x3Fu || c == 0x80u) lf = 1;
        if ((i & 3) && c)             lb = 1;
    }
    if (lf) atomicOr(&s_float, 1);
    if (lb) atomicOr(&s_byte, 1);
    __syncthreads();

    const bool word = (s_float != 0) || (s_byte == 0);
    const unsigned int* mw = (const unsigned int*)mraw;
    for (int i = tid; i < M_; i += 1024)
        g_mask[i] = word ? (mw[i] != 0u ? 1 : 0) : (mraw[i] ? 1 : 0);
}

// ---------------------------------------------------------------------------
// GEMM: C[M,N] = A[M,K] @ W[N,K]^T   (row-major; K = N = 1024)
// 128x128 tile, BK=8, 256 threads, 8x8 per thread.
// MODE: 0 = none, 1 = phi, 2 = phi + mask-zero, 3 = mask-zero
// DST : 0 -> C arg, 1 -> g_Q, 2 -> g_KT, 3 -> g_V ; SRC: 0 -> A arg, 1 -> g_KT
// phi(x) = elu(x)+1 = (x>0 ? x+1 : exp(x))
// ---------------------------------------------------------------------------
template <int MODE, int SRC, int DST>
__global__ __launch_bounds__(256, 2)
void gemm128(const float* __restrict__ Aarg, const float* __restrict__ W,
             float* __restrict__ Carg)
{
    const float* A = (SRC == 0) ? Aarg : (const float*)g_KT;
    float* C = (DST == 0) ? Carg : (DST == 1) ? g_Q : (DST == 2) ? g_KT : g_V;

    __shared__ float As[8][128];
    __shared__ float Bs[8][128];

    const int tid   = threadIdx.x;
    const int nBase = blockIdx.x * 128;
    const int mBase = blockIdx.y * 128;
    const int tx = tid & 15;
    const int ty = tid >> 4;

    const int rowL = tid >> 1;
    const int k4   = (tid & 1) * 4;

    const float* Aptr = A + (size_t)(mBase + rowL) * D_ + k4;
    const float* Wptr = W + (size_t)(nBase + rowL) * D_ + k4;

    float acc[8][8];
    #pragma unroll
    for (int i = 0; i < 8; i++)
        #pragma unroll
        for (int j = 0; j < 8; j++) acc[i][j] = 0.f;

    for (int k0 = 0; k0 < D_; k0 += 8) {
        float4 av = *(const float4*)(Aptr + k0);
        float4 wv = *(const float4*)(Wptr + k0);
        As[k4 + 0][rowL] = av.x; As[k4 + 1][rowL] = av.y;
        As[k4 + 2][rowL] = av.z; As[k4 + 3][rowL] = av.w;
        Bs[k4 + 0][rowL] = wv.x; Bs[k4 + 1][rowL] = wv.y;
        Bs[k4 + 2][rowL] = wv.z; Bs[k4 + 3][rowL] = wv.w;
        __syncthreads();

        #pragma unroll
        for (int kk = 0; kk < 8; kk++) {
            float ar[8], br[8];
            *(float4*)(ar)     = *(const float4*)&As[kk][ty * 8];
            *(float4*)(ar + 4) = *(const float4*)&As[kk][ty * 8 + 4];
            *(float4*)(br)     = *(const float4*)&Bs[kk][tx * 8];
            *(float4*)(br + 4) = *(const float4*)&Bs[kk][tx * 8 + 4];
            #pragma unroll
            for (int i = 0; i < 8; i++)
                #pragma unroll
                for (int j = 0; j < 8; j++)
                    acc[i][j] = fmaf(ar[i], br[j], acc[i][j]);
        }
        __syncthreads();
    }

    #pragma unroll
    for (int i = 0; i < 8; i++) {
        const int m = mBase + ty * 8 + i;
        unsigned char mz = 0;
        if (MODE == 2 || MODE == 3) mz = g_mask[m];
        float* crow = C + (size_t)m * D_ + nBase + tx * 8;
        #pragma unroll
        for (int j = 0; j < 8; j++) {
            float c = acc[i][j];
            if (MODE == 1 || MODE == 2)
                c = (c > 0.f) ? (c + 1.f) : expf(c);
            if ((MODE == 2 || MODE == 3) && mz)
                c = 0.f;
            crow[j] = c;
        }
    }
}

// ---------------------------------------------------------------------------
// kv[b,h] = sum_t k[t]^T v[t]  (64x64) ;  k_sum[b,h] = sum_t k[t]
// ---------------------------------------------------------------------------
__global__ __launch_bounds__(256)
void kv_reduce()
{
    const int bh = blockIdx.x;
    const int b  = bh / H_;
    const int h  = bh % H_;

    __shared__ float ks[32][64];
    __shared__ float vs[32][64];

    const int tid = threadIdx.x;
    const int d   = tid & 63;
    const int eb  = (tid >> 6) * 16;

    float acc[16];
    #pragma unroll
    for (int j = 0; j < 16; j++) acc[j] = 0.f;
    float ksum = 0.f;

    const float* Kb = g_KT + (size_t)b * T_ * D_ + h * HD_;
    const float* Vb = g_V  + (size_t)b * T_ * D_ + h * HD_;

    for (int t0 = 0; t0 < T_; t0 += 32) {
        for (int i = tid; i < 512; i += 256) {
            const int r  = i >> 4;
            const int c4 = (i & 15) * 4;
            *(float4*)&ks[r][c4] = *(const float4*)(Kb + (size_t)(t0 + r) * D_ + c4);
            *(float4*)&vs[r][c4] = *(const float4*)(Vb + (size_t)(t0 + r) * D_ + c4);
        }
        __syncthreads();
        #pragma unroll 8
        for (int tt = 0; tt < 32; tt++) {
            const float kd = ks[tt][d];
            if (tid < 64) ksum += kd;
            #pragma unroll
            for (int j = 0; j < 16; j++)
                acc[j] = fmaf(kd, vs[tt][eb + j], acc[j]);
        }
        __syncthreads();
    }

    float* kvout = g_kv + (size_t)bh * HD_ * HD_;
    #pragma unroll
    for (int j = 0; j < 16; j++)
        kvout[d * HD_ + eb + j] = acc[j];
    if (tid < 64)
        g_ksum[bh * HD_ + tid] = ksum;
}

// ---------------------------------------------------------------------------
// tmp[b,t,h,:] = (q @ kv) / max(q . k_sum, 1e-6)   -> writes g_KT
// ---------------------------------------------------------------------------
__global__ __launch_bounds__(256)
void apply_kv()
{
    const int m0 = blockIdx.x * 32;
    const int h  = blockIdx.y;
    const int b  = m0 / T_;

    __shared__ float kvs[64][65];
    __shared__ float qs[32][65];
    __shared__ float kss[64];

    const int tid = threadIdx.x;
    const float* kvin = g_kv + (size_t)(b * H_ + h) * HD_ * HD_;
    for (int i = tid; i < 4096; i += 256)
        kvs[i >> 6][i & 63] = kvin[i];
    if (tid < 64)
        kss[tid] = g_ksum[(b * H_ + h) * HD_ + tid];

    const float* Qb = g_Q + (size_t)m0 * D_ + h * HD_;
    for (int i = tid; i < 512; i += 256) {
        const int r  = i >> 4;
        const int c4 = (i & 15) * 4;
        float4 v = *(const float4*)(Qb + (size_t)r * D_ + c4);
        qs[r][c4] = v.x; qs[r][c4 + 1] = v.y; qs[r][c4 + 2] = v.z; qs[r][c4 + 3] = v.w;
    }
    __syncthreads();

    const int r  = tid >> 3;
    const int eb = (tid & 7) * 8;
    float acc[8];
    #pragma unroll
    for (int j = 0; j < 8; j++) acc[j] = 0.f;
    float norm = 0.f;

    #pragma unroll 16
    for (int dd = 0; dd < 64; dd++) {
        const float qv = qs[r][dd];
        norm = fmaf(qv, kss[dd], norm);
        #pragma unroll
        for (int j = 0; j < 8; j++)
            acc[j] = fmaf(qv, kvs[dd][eb + j], acc[j]);
    }
    const float inv = 1.f / fmaxf(norm, 1e-6f);

    float* outp = g_KT + (size_t)(m0 + r) * D_ + h * HD_ + eb;
    #pragma unroll
    for (int j = 0; j < 8; j++)
        outp[j] = acc[j] * inv;
}

// ---------------------------------------------------------------------------
extern "C" void kernel_launch(void* const* d_in, const int* in_sizes, int n_in,
                              void* d_out, int out_size)
{
    const float*         x    = (const float*)d_in[0];
    const unsigned char* mask = (const unsigned char*)d_in[1];
    const float*         Wq   = (const float*)d_in[2];
    const float*         Wk   = (const float*)d_in[3];
    const float*         Wv   = (const float*)d_in[4];
    const float*         Wo   = (const float*)d_in[5];
    float*               out  = (float*)d_out;

    dim3 gdim(D_ / 128, M_ / 128);
    dim3 bdim(256);

    mask_canon<<<1, 1024>>>(mask);                         // canonical g_mask
    gemm128<1, 0, 1><<<gdim, bdim>>>(x, Wq, nullptr);      // Q  = phi(x Wq^T)
    gemm128<2, 0, 2><<<gdim, bdim>>>(x, Wk, nullptr);      // K  = phi(.) masked
    gemm128<3, 0, 3><<<gdim, bdim>>>(x, Wv, nullptr);      // V  = (.) masked
    kv_reduce<<<B_ * H_, 256>>>();                         // kv, ksum
    apply_kv<<<dim3(M_ / 32, H_), 256>>>();                // tmp -> g_KT
    gemm128<0, 1, 0><<<gdim, bdim>>>(nullptr, Wo, out);    // y = tmp Wo^T
}